// round 13
// baseline (speedup 1.0000x reference)
#include <cuda_runtime.h>
#include <cuda_fp16.h>
#include <cstdint>

#define N_NODES 10000
#define N_EDGES 320000
#define D 256
#define ALPHA 0.2f

// ---------------- scratch (no runtime allocation allowed) ------------------
__device__ __half g_feats_h[N_NODES * D];   // 5.12 MB fp16 gather table
__device__ float  g_a1[N_NODES];
__device__ float  g_a2[N_NODES];
__device__ float  g_u1[D];
__device__ float  g_u2[D];
__device__ float  g_c12[2];
__device__ int    g_rowptr[N_NODES + 1];

__device__ __forceinline__ uint32_t smem_u32(const void* p) {
    uint32_t a;
    asm("{ .reg .u64 t; cvta.to.shared.u64 t, %1; cvt.u32.u64 %0, t; }" : "=r"(a) : "l"(p));
    return a;
}

#define LDMATRIX_X4(r0,r1,r2,r3, addr)                                      \
    asm volatile("ldmatrix.sync.aligned.m8n8.x4.shared.b16 {%0,%1,%2,%3}, [%4];" \
        : "=r"(r0),"=r"(r1),"=r"(r2),"=r"(r3) : "r"(addr))

#define LDMATRIX_X4_T(r0,r1,r2,r3, addr)                                    \
    asm volatile("ldmatrix.sync.aligned.m8n8.x4.trans.shared.b16 {%0,%1,%2,%3}, [%4];" \
        : "=r"(r0),"=r"(r1),"=r"(r2),"=r"(r3) : "r"(addr))

#define MMA_16816(c, a, b0, b1)                                             \
    asm volatile("mma.sync.aligned.m16n8k16.row.col.f32.f16.f16.f32 "       \
        "{%0,%1,%2,%3}, {%4,%5,%6,%7}, {%8,%9}, {%0,%1,%2,%3};"             \
        : "+f"((c)[0]),"+f"((c)[1]),"+f"((c)[2]),"+f"((c)[3])               \
        : "r"((a)[0]),"r"((a)[1]),"r"((a)[2]),"r"((a)[3]), "r"(b0),"r"(b1))

// Gather one fp16 row-slice (8 cols at lane*8) and accumulate with weight e.
#define GATHER_ACC(acc, e, dd)                                              \
    do {                                                                    \
        const uint4 v = *(const uint4*)(featsh + (size_t)(dd) * D + lane * 8); \
        const float2 f0 = __half22float2(*(const __half2*)&v.x);            \
        const float2 f1 = __half22float2(*(const __half2*)&v.y);            \
        const float2 f2 = __half22float2(*(const __half2*)&v.z);            \
        const float2 f3 = __half22float2(*(const __half2*)&v.w);            \
        (acc)[0] += (e) * f0.x; (acc)[1] += (e) * f0.y;                     \
        (acc)[2] += (e) * f1.x; (acc)[3] += (e) * f1.y;                     \
        (acc)[4] += (e) * f2.x; (acc)[5] += (e) * f2.y;                     \
        (acc)[6] += (e) * f3.x; (acc)[7] += (e) * f3.y;                     \
    } while (0)

// ---------------------------------------------------------------------------
// HMMA GEMM + fused adot (unchanged — it works).
// ---------------------------------------------------------------------------
__global__ __launch_bounds__(256) void gemm_mma_kernel(const float* __restrict__ X,
                                                       const float* __restrict__ W,
                                                       const float* __restrict__ b,
                                                       const float* __restrict__ u1,
                                                       const float* __restrict__ u2,
                                                       const float* __restrict__ c12,
                                                       __half* __restrict__ outh,
                                                       float* __restrict__ a1,
                                                       float* __restrict__ a2)
{
    __shared__ __half As[128][40];
    __shared__ __half Bs[32][72];

    const int tid  = threadIdx.x;
    const int wid  = tid >> 5;
    const int lane = tid & 31;
    const int row0 = blockIdx.y * 128;
    const int col0 = blockIdx.x * 64;
    const bool do_adot = (blockIdx.x == 0);

    const int wm0 = (wid & 3) * 32;
    const int wn0 = (wid >> 2) * 32;

    const int ar  = tid >> 1;
    const int ak0 = (tid & 1) * 16;
    const bool arow_ok = (row0 + ar) < N_NODES;
    const int brw = tid >> 3;
    const int bc0 = (tid & 7) * 8;

    float acc[2][4][4] = {};
    float s1 = 0.f, s2 = 0.f;
    float4 fA[4], fB[2];

    {
        if (arow_ok) {
            const float* src = X + (size_t)(row0 + ar) * D + ak0;
            fA[0] = *(const float4*)(src + 0);
            fA[1] = *(const float4*)(src + 4);
            fA[2] = *(const float4*)(src + 8);
            fA[3] = *(const float4*)(src + 12);
        } else {
            fA[0]=fA[1]=fA[2]=fA[3]=make_float4(0.f,0.f,0.f,0.f);
        }
        const float* bsrc = W + (size_t)brw * D + col0 + bc0;
        fB[0] = *(const float4*)(bsrc + 0);
        fB[1] = *(const float4*)(bsrc + 4);
    }

    #pragma unroll 1
    for (int it = 0; it < 8; it++) {
        const int k0 = it * 32;

        if (do_adot) {
            const float* v1 = u1 + k0 + ak0;
            const float* v2 = u2 + k0 + ak0;
            #pragma unroll
            for (int i = 0; i < 4; i++) {
                const float4 q1 = *(const float4*)(v1 + i * 4);
                const float4 q2 = *(const float4*)(v2 + i * 4);
                s1 += fA[i].x*q1.x + fA[i].y*q1.y + fA[i].z*q1.z + fA[i].w*q1.w;
                s2 += fA[i].x*q2.x + fA[i].y*q2.y + fA[i].z*q2.z + fA[i].w*q2.w;
            }
        }

        {
            union { __half2 h[8]; uint4 u[2]; } pk;
            #pragma unroll
            for (int i = 0; i < 4; i++) {
                pk.h[i*2+0] = __floats2half2_rn(fA[i].x, fA[i].y);
                pk.h[i*2+1] = __floats2half2_rn(fA[i].z, fA[i].w);
            }
            uint4* dst = (uint4*)&As[ar][ak0];
            dst[0] = pk.u[0]; dst[1] = pk.u[1];

            union { __half2 h[4]; uint4 u; } pb;
            pb.h[0] = __floats2half2_rn(fB[0].x, fB[0].y);
            pb.h[1] = __floats2half2_rn(fB[0].z, fB[0].w);
            pb.h[2] = __floats2half2_rn(fB[1].x, fB[1].y);
            pb.h[3] = __floats2half2_rn(fB[1].z, fB[1].w);
            *(uint4*)&Bs[brw][bc0] = pb.u;
        }
        __syncthreads();

        if (it < 7) {
            const int kn = k0 + 32;
            if (arow_ok) {
                const float* src = X + (size_t)(row0 + ar) * D + kn + ak0;
                fA[0] = *(const float4*)(src + 0);
                fA[1] = *(const float4*)(src + 4);
                fA[2] = *(const float4*)(src + 8);
                fA[3] = *(const float4*)(src + 12);
            }
            const float* bsrc = W + (size_t)(kn + brw) * D + col0 + bc0;
            fB[0] = *(const float4*)(bsrc + 0);
            fB[1] = *(const float4*)(bsrc + 4);
        }

        #pragma unroll
        for (int kg = 0; kg < 2; kg++) {
            uint32_t afr[2][4];
            #pragma unroll
            for (int mi = 0; mi < 2; mi++) {
                const uint32_t addr = smem_u32(
                    &As[wm0 + mi*16 + (lane & 15)][kg*16 + ((lane >> 4) << 3)]);
                LDMATRIX_X4(afr[mi][0], afr[mi][1], afr[mi][2], afr[mi][3], addr);
            }
            uint32_t bfr[2][4];
            #pragma unroll
            for (int ng = 0; ng < 2; ng++) {
                const uint32_t addr = smem_u32(
                    &Bs[kg*16 + (lane & 15)][wn0 + ng*16 + ((lane >> 4) << 3)]);
                LDMATRIX_X4_T(bfr[ng][0], bfr[ng][1], bfr[ng][2], bfr[ng][3], addr);
            }
            #pragma unroll
            for (int mi = 0; mi < 2; mi++)
                #pragma unroll
                for (int ni = 0; ni < 4; ni++)
                    MMA_16816(acc[mi][ni], afr[mi],
                              bfr[ni >> 1][(ni & 1) * 2 + 0],
                              bfr[ni >> 1][(ni & 1) * 2 + 1]);
        }
        __syncthreads();
    }

    if (do_adot) {
        s1 += __shfl_xor_sync(0xFFFFFFFFu, s1, 1);
        s2 += __shfl_xor_sync(0xFFFFFFFFu, s2, 1);
        if ((tid & 1) == 0 && arow_ok) {
            a1[row0 + ar] = s1 + c12[0];
            a2[row0 + ar] = s2 + c12[1];
        }
    }

    const int gr = lane >> 2;
    const int gc = (lane & 3) * 2;
    #pragma unroll
    for (int mi = 0; mi < 2; mi++) {
        const int ra = row0 + wm0 + mi*16 + gr;
        const int rb = ra + 8;
        #pragma unroll
        for (int ni = 0; ni < 4; ni++) {
            const int col = col0 + wn0 + ni*8 + gc;
            const float bx = b[col], by = b[col + 1];
            if (ra < N_NODES)
                *(__half2*)(outh + (size_t)ra * D + col) =
                    __floats2half2_rn(acc[mi][ni][0] + bx, acc[mi][ni][1] + by);
            if (rb < N_NODES)
                *(__half2*)(outh + (size_t)rb * D + col) =
                    __floats2half2_rn(acc[mi][ni][2] + bx, acc[mi][ni][3] + by);
        }
    }
}

// ---------------------------------------------------------------------------
__global__ void u_kernel(const float* __restrict__ W,
                         const float* __restrict__ b1,
                         const float* __restrict__ Wa,
                         float* __restrict__ u1, float* __restrict__ u2,
                         float* __restrict__ c12)
{
    const int w = (blockIdx.x * blockDim.x + threadIdx.x) >> 5;
    const int lane = threadIdx.x & 31;
    if (w >= D + 1) return;

    const float* vec = (w < D) ? (W + (size_t)w * D) : b1;
    float s1 = 0.f, s2 = 0.f;
    #pragma unroll
    for (int i = 0; i < 2; i++) {
        const int off = lane * 8 + i * 4;
        const float4 fv = *(const float4*)(vec + off);
        const float4 w1 = *(const float4*)(Wa + off);
        const float4 w2 = *(const float4*)(Wa + D + off);
        s1 += fv.x*w1.x + fv.y*w1.y + fv.z*w1.z + fv.w*w1.w;
        s2 += fv.x*w2.x + fv.y*w2.y + fv.z*w2.z + fv.w*w2.w;
    }
    #pragma unroll
    for (int o = 16; o > 0; o >>= 1) {
        s1 += __shfl_xor_sync(0xFFFFFFFFu, s1, o);
        s2 += __shfl_xor_sync(0xFFFFFFFFu, s2, o);
    }
    if (lane == 0) {
        if (w < D) { u1[w] = s1; u2[w] = s2; }
        else       { c12[0] = s1; c12[1] = s2; }
    }
}

// ---------------------------------------------------------------------------
__global__ void rowptr_kernel(const int* __restrict__ edges,
                              int* __restrict__ rowptr)
{
    const int e = blockIdx.x * blockDim.x + threadIdx.x;
    if (e >= N_EDGES) return;
    const int s    = edges[2 * e];
    const int prev = (e == 0) ? -1 : edges[2 * (e - 1)];
    for (int j = prev + 1; j <= s; j++) rowptr[j] = e;
    if (e == N_EDGES - 1)
        for (int j = s + 1; j <= N_NODES; j++) rowptr[j] = N_EDGES;
}

// ---------------------------------------------------------------------------
// Aggregation v3: ONE warp owns TWO nodes (2w, 2w+1) with interleaved edge
// chains. Per chunk: lanes compute exp-scores for both nodes' edges; inner
// loop issues two independent gathers (A edge j, B edge j) per iteration ->
// 2x MLP at any degree. den accumulated per-lane at score time, warp-reduced
// once at the end. Guards are warp-uniform.
// ---------------------------------------------------------------------------
__global__ __launch_bounds__(256) void agg_kernel(const int* __restrict__ edges,
                                                  const __half* __restrict__ featsh,
                                                  const float* __restrict__ a1,
                                                  const float* __restrict__ a2,
                                                  const float* __restrict__ ba,
                                                  const int* __restrict__ rowptr,
                                                  float* __restrict__ out)
{
    const int w    = (blockIdx.x * blockDim.x + threadIdx.x) >> 5;
    const int lane = threadIdx.x & 31;
    const int iA   = w * 2;
    const int iB   = iA + 1;
    if (iA >= N_NODES) return;

    const float bav = ba[0];
    const int eA0 = rowptr[iA], eA1 = rowptr[iA + 1];
    const int eB0 = rowptr[iB], eB1 = rowptr[iB + 1];
    const float a1A = a1[iA] + bav;
    const float a1B = a1[iB] + bav;

    float accA[8] = {}, accB[8] = {};
    float denA = 0.f, denB = 0.f;

    int baseA = eA0, baseB = eB0;
    while (baseA < eA1 || baseB < eB1) {
        int cntA = eA1 - baseA; cntA = cntA < 0 ? 0 : (cntA > 32 ? 32 : cntA);
        int cntB = eB1 - baseB; cntB = cntB < 0 ? 0 : (cntB > 32 ? 32 : cntB);

        float exA = 0.f, exB = 0.f;
        int dA = 0, dB = 0;
        if (lane < cntA) {
            dA = edges[2 * (baseA + lane) + 1];
            float s = a1A + a2[dA];
            s = (s > 0.f) ? s : (ALPHA * s);
            exA = expf(s);
        }
        if (lane < cntB) {
            dB = edges[2 * (baseB + lane) + 1];
            float s = a1B + a2[dB];
            s = (s > 0.f) ? s : (ALPHA * s);
            exB = expf(s);
        }
        denA += exA;
        denB += exB;

        const int jm = cntA > cntB ? cntA : cntB;
        #pragma unroll 4
        for (int j = 0; j < jm; j++) {
            if (j < cntA) {
                const float e = __shfl_sync(0xFFFFFFFFu, exA, j);
                const int  dd = __shfl_sync(0xFFFFFFFFu, dA,  j);
                GATHER_ACC(accA, e, dd);
            }
            if (j < cntB) {
                const float e = __shfl_sync(0xFFFFFFFFu, exB, j);
                const int  dd = __shfl_sync(0xFFFFFFFFu, dB,  j);
                GATHER_ACC(accB, e, dd);
            }
        }
        baseA += 32;
        baseB += 32;
    }

    // warp-reduce denominators
    #pragma unroll
    for (int o = 16; o > 0; o >>= 1) {
        denA += __shfl_xor_sync(0xFFFFFFFFu, denA, o);
        denB += __shfl_xor_sync(0xFFFFFFFFu, denB, o);
    }

    const float invA = (eA1 > eA0) ? (1.f / denA) : 0.f;
    const float invB = (eB1 > eB0) ? (1.f / denB) : 0.f;

    float4 o0 = make_float4(accA[0]*invA, accA[1]*invA, accA[2]*invA, accA[3]*invA);
    float4 o1 = make_float4(accA[4]*invA, accA[5]*invA, accA[6]*invA, accA[7]*invA);
    *(float4*)(out + (size_t)iA * D + lane * 8)     = o0;
    *(float4*)(out + (size_t)iA * D + lane * 8 + 4) = o1;

    float4 p0 = make_float4(accB[0]*invB, accB[1]*invB, accB[2]*invB, accB[3]*invB);
    float4 p1 = make_float4(accB[4]*invB, accB[5]*invB, accB[6]*invB, accB[7]*invB);
    *(float4*)(out + (size_t)iB * D + lane * 8)     = p0;
    *(float4*)(out + (size_t)iB * D + lane * 8 + 4) = p1;
}

// ---------------------------------------------------------------------------
extern "C" void kernel_launch(void* const* d_in, const int* in_sizes, int n_in,
                              void* d_out, int out_size)
{
    const float* X   = (const float*)d_in[0];
    const int*   edg = (const int*)d_in[1];
    const float* W1  = (const float*)d_in[2];
    const float* b1  = (const float*)d_in[3];
    const float* Wa  = (const float*)d_in[4];
    const float* ba  = (const float*)d_in[5];
    float*       out = (float*)d_out;

    __half* featsh; cudaGetSymbolAddress((void**)&featsh, g_feats_h);
    float*  a1;     cudaGetSymbolAddress((void**)&a1,     g_a1);
    float*  a2;     cudaGetSymbolAddress((void**)&a2,     g_a2);
    float*  u1;     cudaGetSymbolAddress((void**)&u1,     g_u1);
    float*  u2;     cudaGetSymbolAddress((void**)&u2,     g_u2);
    float*  c12;    cudaGetSymbolAddress((void**)&c12,    g_c12);
    int*    rowptr; cudaGetSymbolAddress((void**)&rowptr, g_rowptr);

    rowptr_kernel<<<(N_EDGES + 255) / 256, 256>>>(edg, rowptr);
    u_kernel<<<((D + 1) * 32 + 255) / 256, 256>>>(W1, b1, Wa, u1, u2, c12);

    dim3 ggrid(D / 64, (N_NODES + 127) / 128);   // 4 x 79 = 316 CTAs
    gemm_mma_kernel<<<ggrid, 256>>>(X, W1, b1, u1, u2, c12, featsh, a1, a2);

    // 5000 warps, 8 warps/block -> 625 blocks
    agg_kernel<<<(N_NODES / 2 * 32 + 255) / 256, 256>>>(edg, featsh, a1, a2, ba, rowptr, out);
}

// round 15
// speedup vs baseline: 1.7704x; 1.7704x over previous
#include <cuda_runtime.h>
#include <cuda_fp16.h>
#include <cstdint>

#define N_NODES 10000
#define N_EDGES 320000
#define D 256
#define ALPHA 0.2f

// ---------------- scratch (no runtime allocation allowed) ------------------
__device__ __half g_feats_h[N_NODES * D];   // 5.12 MB fp16 gather table
__device__ float  g_a1[N_NODES];
__device__ float  g_a2[N_NODES];
__device__ float  g_u1[D];
__device__ float  g_u2[D];
__device__ float  g_c12[2];
__device__ int    g_rowptr[N_NODES + 1];

__device__ __forceinline__ uint32_t smem_u32(const void* p) {
    uint32_t a;
    asm("{ .reg .u64 t; cvta.to.shared.u64 t, %1; cvt.u32.u64 %0, t; }" : "=r"(a) : "l"(p));
    return a;
}

#define LDMATRIX_X4(r0,r1,r2,r3, addr)                                      \
    asm volatile("ldmatrix.sync.aligned.m8n8.x4.shared.b16 {%0,%1,%2,%3}, [%4];" \
        : "=r"(r0),"=r"(r1),"=r"(r2),"=r"(r3) : "r"(addr))

#define LDMATRIX_X4_T(r0,r1,r2,r3, addr)                                    \
    asm volatile("ldmatrix.sync.aligned.m8n8.x4.trans.shared.b16 {%0,%1,%2,%3}, [%4];" \
        : "=r"(r0),"=r"(r1),"=r"(r2),"=r"(r3) : "r"(addr))

#define MMA_16816(c, a, b0, b1)                                             \
    asm volatile("mma.sync.aligned.m16n8k16.row.col.f32.f16.f16.f32 "       \
        "{%0,%1,%2,%3}, {%4,%5,%6,%7}, {%8,%9}, {%0,%1,%2,%3};"             \
        : "+f"((c)[0]),"+f"((c)[1]),"+f"((c)[2]),"+f"((c)[3])               \
        : "r"((a)[0]),"r"((a)[1]),"r"((a)[2]),"r"((a)[3]), "r"(b0),"r"(b1))

#define ACC_V(acc, e, v)                                                    \
    do {                                                                    \
        const float2 f0 = __half22float2(*(const __half2*)&(v).x);          \
        const float2 f1 = __half22float2(*(const __half2*)&(v).y);          \
        const float2 f2 = __half22float2(*(const __half2*)&(v).z);          \
        const float2 f3 = __half22float2(*(const __half2*)&(v).w);          \
        (acc)[0] += (e) * f0.x; (acc)[1] += (e) * f0.y;                     \
        (acc)[2] += (e) * f1.x; (acc)[3] += (e) * f1.y;                     \
        (acc)[4] += (e) * f2.x; (acc)[5] += (e) * f2.y;                     \
        (acc)[6] += (e) * f3.x; (acc)[7] += (e) * f3.y;                     \
    } while (0)

// ---------------------------------------------------------------------------
// HMMA GEMM + fused adot (unchanged — it works).
// ---------------------------------------------------------------------------
__global__ __launch_bounds__(256) void gemm_mma_kernel(const float* __restrict__ X,
                                                       const float* __restrict__ W,
                                                       const float* __restrict__ b,
                                                       const float* __restrict__ u1,
                                                       const float* __restrict__ u2,
                                                       const float* __restrict__ c12,
                                                       __half* __restrict__ outh,
                                                       float* __restrict__ a1,
                                                       float* __restrict__ a2)
{
    __shared__ __half As[128][40];
    __shared__ __half Bs[32][72];

    const int tid  = threadIdx.x;
    const int wid  = tid >> 5;
    const int lane = tid & 31;
    const int row0 = blockIdx.y * 128;
    const int col0 = blockIdx.x * 64;
    const bool do_adot = (blockIdx.x == 0);

    const int wm0 = (wid & 3) * 32;
    const int wn0 = (wid >> 2) * 32;

    const int ar  = tid >> 1;
    const int ak0 = (tid & 1) * 16;
    const bool arow_ok = (row0 + ar) < N_NODES;
    const int brw = tid >> 3;
    const int bc0 = (tid & 7) * 8;

    float acc[2][4][4] = {};
    float s1 = 0.f, s2 = 0.f;
    float4 fA[4], fB[2];

    {
        if (arow_ok) {
            const float* src = X + (size_t)(row0 + ar) * D + ak0;
            fA[0] = *(const float4*)(src + 0);
            fA[1] = *(const float4*)(src + 4);
            fA[2] = *(const float4*)(src + 8);
            fA[3] = *(const float4*)(src + 12);
        } else {
            fA[0]=fA[1]=fA[2]=fA[3]=make_float4(0.f,0.f,0.f,0.f);
        }
        const float* bsrc = W + (size_t)brw * D + col0 + bc0;
        fB[0] = *(const float4*)(bsrc + 0);
        fB[1] = *(const float4*)(bsrc + 4);
    }

    #pragma unroll 1
    for (int it = 0; it < 8; it++) {
        const int k0 = it * 32;

        if (do_adot) {
            const float* v1 = u1 + k0 + ak0;
            const float* v2 = u2 + k0 + ak0;
            #pragma unroll
            for (int i = 0; i < 4; i++) {
                const float4 q1 = *(const float4*)(v1 + i * 4);
                const float4 q2 = *(const float4*)(v2 + i * 4);
                s1 += fA[i].x*q1.x + fA[i].y*q1.y + fA[i].z*q1.z + fA[i].w*q1.w;
                s2 += fA[i].x*q2.x + fA[i].y*q2.y + fA[i].z*q2.z + fA[i].w*q2.w;
            }
        }

        {
            union { __half2 h[8]; uint4 u[2]; } pk;
            #pragma unroll
            for (int i = 0; i < 4; i++) {
                pk.h[i*2+0] = __floats2half2_rn(fA[i].x, fA[i].y);
                pk.h[i*2+1] = __floats2half2_rn(fA[i].z, fA[i].w);
            }
            uint4* dst = (uint4*)&As[ar][ak0];
            dst[0] = pk.u[0]; dst[1] = pk.u[1];

            union { __half2 h[4]; uint4 u; } pb;
            pb.h[0] = __floats2half2_rn(fB[0].x, fB[0].y);
            pb.h[1] = __floats2half2_rn(fB[0].z, fB[0].w);
            pb.h[2] = __floats2half2_rn(fB[1].x, fB[1].y);
            pb.h[3] = __floats2half2_rn(fB[1].z, fB[1].w);
            *(uint4*)&Bs[brw][bc0] = pb.u;
        }
        __syncthreads();

        if (it < 7) {
            const int kn = k0 + 32;
            if (arow_ok) {
                const float* src = X + (size_t)(row0 + ar) * D + kn + ak0;
                fA[0] = *(const float4*)(src + 0);
                fA[1] = *(const float4*)(src + 4);
                fA[2] = *(const float4*)(src + 8);
                fA[3] = *(const float4*)(src + 12);
            }
            const float* bsrc = W + (size_t)(kn + brw) * D + col0 + bc0;
            fB[0] = *(const float4*)(bsrc + 0);
            fB[1] = *(const float4*)(bsrc + 4);
        }

        #pragma unroll
        for (int kg = 0; kg < 2; kg++) {
            uint32_t afr[2][4];
            #pragma unroll
            for (int mi = 0; mi < 2; mi++) {
                const uint32_t addr = smem_u32(
                    &As[wm0 + mi*16 + (lane & 15)][kg*16 + ((lane >> 4) << 3)]);
                LDMATRIX_X4(afr[mi][0], afr[mi][1], afr[mi][2], afr[mi][3], addr);
            }
            uint32_t bfr[2][4];
            #pragma unroll
            for (int ng = 0; ng < 2; ng++) {
                const uint32_t addr = smem_u32(
                    &Bs[kg*16 + (lane & 15)][wn0 + ng*16 + ((lane >> 4) << 3)]);
                LDMATRIX_X4_T(bfr[ng][0], bfr[ng][1], bfr[ng][2], bfr[ng][3], addr);
            }
            #pragma unroll
            for (int mi = 0; mi < 2; mi++)
                #pragma unroll
                for (int ni = 0; ni < 4; ni++)
                    MMA_16816(acc[mi][ni], afr[mi],
                              bfr[ni >> 1][(ni & 1) * 2 + 0],
                              bfr[ni >> 1][(ni & 1) * 2 + 1]);
        }
        __syncthreads();
    }

    if (do_adot) {
        s1 += __shfl_xor_sync(0xFFFFFFFFu, s1, 1);
        s2 += __shfl_xor_sync(0xFFFFFFFFu, s2, 1);
        if ((tid & 1) == 0 && arow_ok) {
            a1[row0 + ar] = s1 + c12[0];
            a2[row0 + ar] = s2 + c12[1];
        }
    }

    const int gr = lane >> 2;
    const int gc = (lane & 3) * 2;
    #pragma unroll
    for (int mi = 0; mi < 2; mi++) {
        const int ra = row0 + wm0 + mi*16 + gr;
        const int rb = ra + 8;
        #pragma unroll
        for (int ni = 0; ni < 4; ni++) {
            const int col = col0 + wn0 + ni*8 + gc;
            const float bx = b[col], by = b[col + 1];
            if (ra < N_NODES)
                *(__half2*)(outh + (size_t)ra * D + col) =
                    __floats2half2_rn(acc[mi][ni][0] + bx, acc[mi][ni][1] + by);
            if (rb < N_NODES)
                *(__half2*)(outh + (size_t)rb * D + col) =
                    __floats2half2_rn(acc[mi][ni][2] + bx, acc[mi][ni][3] + by);
        }
    }
}

// ---------------------------------------------------------------------------
// Prep kernel: blocks [0, NB_RP) build CSR rowptr; blocks [NB_RP, ..) compute
// u1 = W1@wa1, u2 = W1@wa2, c12 = b1.Wa (one warp per W row).
// ---------------------------------------------------------------------------
#define NB_RP ((N_EDGES + 255) / 256)

__global__ void prep_kernel(const int* __restrict__ edges,
                            int* __restrict__ rowptr,
                            const float* __restrict__ W,
                            const float* __restrict__ b1,
                            const float* __restrict__ Wa,
                            float* __restrict__ u1, float* __restrict__ u2,
                            float* __restrict__ c12)
{
    if (blockIdx.x < NB_RP) {
        const int e = blockIdx.x * 256 + threadIdx.x;
        if (e >= N_EDGES) return;
        const int s    = edges[2 * e];
        const int prev = (e == 0) ? -1 : edges[2 * (e - 1)];
        for (int j = prev + 1; j <= s; j++) rowptr[j] = e;
        if (e == N_EDGES - 1)
            for (int j = s + 1; j <= N_NODES; j++) rowptr[j] = N_EDGES;
        return;
    }

    const int w = ((blockIdx.x - NB_RP) * 256 + threadIdx.x) >> 5;
    const int lane = threadIdx.x & 31;
    if (w >= D + 1) return;

    const float* vec = (w < D) ? (W + (size_t)w * D) : b1;
    float s1 = 0.f, s2 = 0.f;
    #pragma unroll
    for (int i = 0; i < 2; i++) {
        const int off = lane * 8 + i * 4;
        const float4 fv = *(const float4*)(vec + off);
        const float4 w1 = *(const float4*)(Wa + off);
        const float4 w2 = *(const float4*)(Wa + D + off);
        s1 += fv.x*w1.x + fv.y*w1.y + fv.z*w1.z + fv.w*w1.w;
        s2 += fv.x*w2.x + fv.y*w2.y + fv.z*w2.z + fv.w*w2.w;
    }
    #pragma unroll
    for (int o = 16; o > 0; o >>= 1) {
        s1 += __shfl_xor_sync(0xFFFFFFFFu, s1, o);
        s2 += __shfl_xor_sync(0xFFFFFFFFu, s2, o);
    }
    if (lane == 0) {
        if (w < D) { u1[w] = s1; u2[w] = s2; }
        else       { c12[0] = s1; c12[1] = s2; }
    }
}

// ---------------------------------------------------------------------------
// Aggregation v4: ONE warp per node (max TLP), explicit batch-8 gathers.
// Per 32-edge chunk: lanes compute exp(score); inner loop issues 8
// shfl+LDG.128 into registers, then 8 accumulate blocks -> 8 loads
// guaranteed in flight, no guards inside the batch. Scalar tail.
// ---------------------------------------------------------------------------
__global__ __launch_bounds__(256) void agg_kernel(const int* __restrict__ edges,
                                                  const __half* __restrict__ featsh,
                                                  const float* __restrict__ a1,
                                                  const float* __restrict__ a2,
                                                  const float* __restrict__ ba,
                                                  const int* __restrict__ rowptr,
                                                  float* __restrict__ out)
{
    const int i    = (blockIdx.x * blockDim.x + threadIdx.x) >> 5;
    const int lane = threadIdx.x & 31;
    if (i >= N_NODES) return;

    const int e0 = rowptr[i];
    const int e1 = rowptr[i + 1];
    const float a1i = a1[i] + ba[0];

    float acc[8] = {};
    float den = 0.f;

    for (int base = e0; base < e1; base += 32) {
        const int cnt = min(32, e1 - base);
        int d = 0;
        float ex = 0.f;
        if (lane < cnt) {
            d = edges[2 * (base + lane) + 1];
            float s = a1i + a2[d];
            s = (s > 0.f) ? s : (ALPHA * s);
            ex = expf(s);
        }
        den += ex;   // per-lane partial; reduced once at the end

        int j = 0;
        for (; j + 8 <= cnt; j += 8) {
            uint4 v[8];
            float e[8];
            #pragma unroll
            for (int k = 0; k < 8; k++) {
                e[k] = __shfl_sync(0xFFFFFFFFu, ex, j + k);
                const int dd = __shfl_sync(0xFFFFFFFFu, d, j + k);
                v[k] = *(const uint4*)(featsh + (size_t)dd * D + lane * 8);
            }
            #pragma unroll
            for (int k = 0; k < 8; k++)
                ACC_V(acc, e[k], v[k]);
        }
        for (; j < cnt; j++) {
            const float e = __shfl_sync(0xFFFFFFFFu, ex, j);
            const int  dd = __shfl_sync(0xFFFFFFFFu, d, j);
            const uint4 v = *(const uint4*)(featsh + (size_t)dd * D + lane * 8);
            ACC_V(acc, e, v);
        }
    }

    #pragma unroll
    for (int o = 16; o > 0; o >>= 1)
        den += __shfl_xor_sync(0xFFFFFFFFu, den, o);

    const float inv = (e1 > e0) ? (1.f / den) : 0.f;
    float4 o0 = make_float4(acc[0]*inv, acc[1]*inv, acc[2]*inv, acc[3]*inv);
    float4 o1 = make_float4(acc[4]*inv, acc[5]*inv, acc[6]*inv, acc[7]*inv);
    *(float4*)(out + (size_t)i * D + lane * 8)     = o0;
    *(float4*)(out + (size_t)i * D + lane * 8 + 4) = o1;
}

// ---------------------------------------------------------------------------
extern "C" void kernel_launch(void* const* d_in, const int* in_sizes, int n_in,
                              void* d_out, int out_size)
{
    const float* X   = (const float*)d_in[0];
    const int*   edg = (const int*)d_in[1];
    const float* W1  = (const float*)d_in[2];
    const float* b1  = (const float*)d_in[3];
    const float* Wa  = (const float*)d_in[4];
    const float* ba  = (const float*)d_in[5];
    float*       out = (float*)d_out;

    __half* featsh; cudaGetSymbolAddress((void**)&featsh, g_feats_h);
    float*  a1;     cudaGetSymbolAddress((void**)&a1,     g_a1);
    float*  a2;     cudaGetSymbolAddress((void**)&a2,     g_a2);
    float*  u1;     cudaGetSymbolAddress((void**)&u1,     g_u1);
    float*  u2;     cudaGetSymbolAddress((void**)&u2,     g_u2);
    float*  c12;    cudaGetSymbolAddress((void**)&c12,    g_c12);
    int*    rowptr; cudaGetSymbolAddress((void**)&rowptr, g_rowptr);

    const int nb_u = ((D + 1) * 32 + 255) / 256;   // 33
    prep_kernel<<<NB_RP + nb_u, 256>>>(edg, rowptr, W1, b1, Wa, u1, u2, c12);

    dim3 ggrid(D / 64, (N_NODES + 127) / 128);   // 4 x 79 = 316 CTAs
    gemm_mma_kernel<<<ggrid, 256>>>(X, W1, b1, u1, u2, c12, featsh, a1, a2);

    // one warp per node: 10000 warps -> 1250 blocks
    agg_kernel<<<(N_NODES * 32 + 255) / 256, 256>>>(edg, featsh, a1, a2, ba, rowptr, out);
}